// round 1
// baseline (speedup 1.0000x reference)
#include <cuda_runtime.h>

#define BB 4
#define LL 1024
#define DD 128
#define HH 8
#define GG 64
#define NEGV -1000000000.0f
#define NITER 4

// ---------------- scratch (static device arrays; no allocations) ----------------
__device__ float g_Qz[BB*LL*DD];                 // softmax(F_Z)
__device__ float g_P [BB*HH*LL*DD];              // Qz @ T_h
__device__ float g_U [BB*HH*LL*DD];              // Qz @ T_h^T
__device__ float g_S [(size_t)BB*HH*LL*LL];      // F_Hs / Qhs  (134 MB)
__device__ float g_Hg[BB*HH*LL*GG];              // F_Hg / Qhg
__device__ float g_FZ[BB*LL*DD];                 // F_Z accumulator
__device__ float g_Tp[HH*DD*DD];                 // T[h][a][b]
__device__ float g_Tt[HH*DD*DD];                 // T[h][b][a]
__device__ float g_Gp[HH*GG*DD];                 // global_[h][g][a]

// ---------------- repack weights ----------------
__global__ void k_repack(const float* __restrict__ ternary, const float* __restrict__ glob) {
  int idx = blockIdx.x*256 + threadIdx.x;
  if (idx < DD*DD*HH) {
    int h = idx % HH; int ab = idx / HH; int b = ab % DD; int a = ab / DD;
    float v = ternary[idx];
    g_Tp[h*DD*DD + a*DD + b] = v;
    g_Tt[h*DD*DD + b*DD + a] = v;
  }
  if (idx < GG*DD*HH) {
    int h = idx % HH; int ga = idx / HH; int a = ga % DD; int g = ga / DD;
    g_Gp[h*GG*DD + g*DD + a] = glob[idx];
  }
}

// ---------------- softmax over D=128 (rows of x or F_Z -> Qz) ----------------
__global__ void k_softmax_z(const float* __restrict__ x, int use_fz) {
  const float* in = use_fz ? g_FZ : x;
  int row = blockIdx.x;
  int t = threadIdx.x;            // 128
  float v = in[row*DD + t];
  __shared__ float r1[4], r2[4];
  float m = v;
  #pragma unroll
  for (int o=16;o;o>>=1) m = fmaxf(m, __shfl_xor_sync(0xffffffffu, m, o));
  if ((t&31)==0) r1[t>>5] = m;
  __syncthreads();
  m = fmaxf(fmaxf(r1[0],r1[1]), fmaxf(r1[2],r1[3]));
  float e = __expf(v - m);
  float s = e;
  #pragma unroll
  for (int o=16;o;o>>=1) s += __shfl_xor_sync(0xffffffffu, s, o);
  if ((t&31)==0) r2[t>>5] = s;
  __syncthreads();
  s = r2[0]+r2[1]+r2[2]+r2[3];
  g_Qz[row*DD + t] = e * (1.0f/s);
}

// ---------------- P = Qz @ T_h  /  U = Qz @ T_h^T  (NN, M=1024,N=128,K=128) ----------------
__global__ __launch_bounds__(256) void k_gemm_zT(int which) {
  const float* __restrict__ Bpack = which ? g_Tt : g_Tp;
  float* __restrict__ Cout = which ? g_U : g_P;
  int z = blockIdx.z; int n = z >> 3; int h = z & 7;
  const float* __restrict__ A  = g_Qz + n*LL*DD;
  const float* __restrict__ Bm = Bpack + h*DD*DD;
  float* __restrict__ C = Cout + (size_t)z*LL*DD;
  int m0 = blockIdx.x * 128;
  __shared__ float As[16][129];
  __shared__ float Bs[16][128];
  int tid = threadIdx.x;
  int lr = tid >> 2, lk = (tid & 3)*4;
  int bk = tid >> 5, bn = (tid & 31)*4;
  int rc = (tid >> 4)*4, cc = (tid & 15)*4;
  float acc[8][8];
  #pragma unroll
  for (int i=0;i<8;i++)
    #pragma unroll
    for (int j=0;j<8;j++) acc[i][j] = 0.f;
  for (int k0=0;k0<DD;k0+=16) {
    #pragma unroll
    for (int s=0;s<2;s++) {
      int m = lr + 64*s;
      float4 v = *(const float4*)(A + (m0+m)*DD + k0 + lk);
      As[lk+0][m]=v.x; As[lk+1][m]=v.y; As[lk+2][m]=v.z; As[lk+3][m]=v.w;
    }
    #pragma unroll
    for (int s=0;s<2;s++) {
      int k = bk + 8*s;
      *(float4*)&Bs[k][bn] = *(const float4*)(Bm + (k0+k)*DD + bn);
    }
    __syncthreads();
    #pragma unroll
    for (int k=0;k<16;k++) {
      float ar[8], br[8];
      #pragma unroll
      for (int i=0;i<4;i++) { ar[i]=As[k][rc+i]; ar[i+4]=As[k][rc+64+i]; }
      float4 b0 = *(const float4*)&Bs[k][cc];
      float4 b1 = *(const float4*)&Bs[k][cc+64];
      br[0]=b0.x; br[1]=b0.y; br[2]=b0.z; br[3]=b0.w;
      br[4]=b1.x; br[5]=b1.y; br[6]=b1.z; br[7]=b1.w;
      #pragma unroll
      for (int i=0;i<8;i++)
        #pragma unroll
        for (int j=0;j<8;j++)
          acc[i][j] += ar[i]*br[j];
    }
    __syncthreads();
  }
  #pragma unroll
  for (int i=0;i<8;i++) {
    int row = m0 + rc + (i&3) + (i>>2)*64;
    *(float4*)(C + row*DD + cc)      = make_float4(acc[i][0],acc[i][1],acc[i][2],acc[i][3]);
    *(float4*)(C + row*DD + cc + 64) = make_float4(acc[i][4],acc[i][5],acc[i][6],acc[i][7]);
  }
}

// ---------------- F_Hg = Qz @ Gp_h^T (NT, M=1024,N=64,K=128) ----------------
__global__ __launch_bounds__(256) void k_gemm_hg() {
  int z = blockIdx.z; int n = z >> 3; int h = z & 7;
  const float* __restrict__ A  = g_Qz + n*LL*DD;
  const float* __restrict__ Bm = g_Gp + h*GG*DD;   // [g][a], ldb=DD
  float* __restrict__ C = g_Hg + (size_t)z*LL*GG;
  int m0 = blockIdx.x * 128;
  __shared__ float As[16][129];
  __shared__ float Bs[16][65];
  int tid = threadIdx.x;
  int lr = tid >> 2, lk = (tid & 3)*4;
  int rc = (tid >> 4)*4, cc = (tid & 15)*4;
  float acc[8][4];
  #pragma unroll
  for (int i=0;i<8;i++)
    #pragma unroll
    for (int j=0;j<4;j++) acc[i][j] = 0.f;
  for (int k0=0;k0<DD;k0+=16) {
    #pragma unroll
    for (int s=0;s<2;s++) {
      int m = lr + 64*s;
      float4 v = *(const float4*)(A + (m0+m)*DD + k0 + lk);
      As[lk+0][m]=v.x; As[lk+1][m]=v.y; As[lk+2][m]=v.z; As[lk+3][m]=v.w;
    }
    {
      float4 v = *(const float4*)(Bm + lr*DD + k0 + lk);
      Bs[lk+0][lr]=v.x; Bs[lk+1][lr]=v.y; Bs[lk+2][lr]=v.z; Bs[lk+3][lr]=v.w;
    }
    __syncthreads();
    #pragma unroll
    for (int k=0;k<16;k++) {
      float ar[8], br[4];
      #pragma unroll
      for (int i=0;i<4;i++) { ar[i]=As[k][rc+i]; ar[i+4]=As[k][rc+64+i]; }
      #pragma unroll
      for (int j=0;j<4;j++) br[j]=Bs[k][cc+j];
      #pragma unroll
      for (int i=0;i<8;i++)
        #pragma unroll
        for (int j=0;j<4;j++)
          acc[i][j] += ar[i]*br[j];
    }
    __syncthreads();
  }
  #pragma unroll
  for (int i=0;i<8;i++) {
    int row = m0 + rc + (i&3) + (i>>2)*64;
    *(float4*)(C + row*GG + cc) = make_float4(acc[i][0],acc[i][1],acc[i][2],acc[i][3]);
  }
}

// ---------------- S = P @ Qz^T (NT, M=N=1024, K=128) ----------------
__global__ __launch_bounds__(256) void k_gemm_s() {
  int z = blockIdx.z; int n = z >> 3;
  const float* __restrict__ A  = g_P  + (size_t)z*LL*DD;
  const float* __restrict__ Bm = g_Qz + n*LL*DD;
  float* __restrict__ C = g_S + (size_t)z*LL*LL;
  int m0 = blockIdx.x*128, n0 = blockIdx.y*128;
  __shared__ float As[16][129];
  __shared__ float Bs[16][129];
  int tid = threadIdx.x;
  int lr = tid >> 2, lk = (tid & 3)*4;
  int rc = (tid >> 4)*4, cc = (tid & 15)*4;
  float acc[8][8];
  #pragma unroll
  for (int i=0;i<8;i++)
    #pragma unroll
    for (int j=0;j<8;j++) acc[i][j] = 0.f;
  for (int k0=0;k0<DD;k0+=16) {
    #pragma unroll
    for (int s=0;s<2;s++) {
      int m = lr + 64*s;
      float4 v = *(const float4*)(A + (m0+m)*DD + k0 + lk);
      As[lk+0][m]=v.x; As[lk+1][m]=v.y; As[lk+2][m]=v.z; As[lk+3][m]=v.w;
    }
    #pragma unroll
    for (int s=0;s<2;s++) {
      int nn = lr + 64*s;
      float4 v = *(const float4*)(Bm + (n0+nn)*DD + k0 + lk);
      Bs[lk+0][nn]=v.x; Bs[lk+1][nn]=v.y; Bs[lk+2][nn]=v.z; Bs[lk+3][nn]=v.w;
    }
    __syncthreads();
    #pragma unroll
    for (int k=0;k<16;k++) {
      float ar[8], br[8];
      #pragma unroll
      for (int i=0;i<4;i++) { ar[i]=As[k][rc+i]; ar[i+4]=As[k][rc+64+i]; }
      #pragma unroll
      for (int j=0;j<4;j++) { br[j]=Bs[k][cc+j]; br[j+4]=Bs[k][cc+64+j]; }
      #pragma unroll
      for (int i=0;i<8;i++)
        #pragma unroll
        for (int j=0;j<8;j++)
          acc[i][j] += ar[i]*br[j];
    }
    __syncthreads();
  }
  #pragma unroll
  for (int i=0;i<8;i++) {
    int row = m0 + rc + (i&3) + (i>>2)*64;
    *(float4*)(C + (size_t)row*LL + n0 + cc)      = make_float4(acc[i][0],acc[i][1],acc[i][2],acc[i][3]);
    *(float4*)(C + (size_t)row*LL + n0 + cc + 64) = make_float4(acc[i][4],acc[i][5],acc[i][6],acc[i][7]);
  }
}

// ---------------- softmax over concat [S row (1024) | Hg row (64)] ----------------
__global__ void k_softmax_h(const int* __restrict__ mask) {
  int r = blockIdx.x;                 // (n*H+h)*L + i
  int t = threadIdx.x;                // 256
  float* Srow = g_S  + (size_t)r*LL;
  float* Hrow = g_Hg + (size_t)r*GG;
  int n = r >> 13;
  int i = r & (LL-1);
  const int* mrow = mask + n*LL;
  int mi = mrow[i];
  float v[4];
  float lm = -3.4e38f;
  #pragma unroll
  for (int s=0;s<4;s++) {
    int j = t + s*256;
    float xv = Srow[j];
    if (!(mi && mrow[j])) xv = NEGV;
    v[s] = xv; lm = fmaxf(lm, xv);
  }
  float hg = 0.f;
  if (t < GG) { hg = Hrow[t]; lm = fmaxf(lm, hg); }
  __shared__ float sm[8], ss[8];
  float w = lm;
  #pragma unroll
  for (int o=16;o;o>>=1) w = fmaxf(w, __shfl_xor_sync(0xffffffffu, w, o));
  if ((t&31)==0) sm[t>>5] = w;
  __syncthreads();
  float m = sm[0];
  #pragma unroll
  for (int q=1;q<8;q++) m = fmaxf(m, sm[q]);
  float sum = 0.f;
  #pragma unroll
  for (int s=0;s<4;s++) { v[s] = __expf(v[s]-m); sum += v[s]; }
  if (t < GG) { hg = __expf(hg-m); sum += hg; }
  #pragma unroll
  for (int o=16;o;o>>=1) sum += __shfl_xor_sync(0xffffffffu, sum, o);
  if ((t&31)==0) ss[t>>5] = sum;
  __syncthreads();
  float tot = 0.f;
  #pragma unroll
  for (int q=0;q<8;q++) tot += ss[q];
  float inv = 1.0f/tot;
  #pragma unroll
  for (int s=0;s<4;s++) Srow[t+s*256] = v[s]*inv;
  if (t < GG) Hrow[t] = hg*inv;
}

// ---------------- F_Z = x ----------------
__global__ void k_init_fz(const float* __restrict__ x) {
  int i = blockIdx.x*256 + threadIdx.x;
  g_FZ[i] = x[i];
}

// ---------------- msg_i: F_Z += Qhs @ U  (NN, K=1024, atomic over h) ----------------
__global__ __launch_bounds__(256) void k_msg_i() {
  int z = blockIdx.z; int n = z >> 3;
  const float* __restrict__ A  = g_S + (size_t)z*LL*LL;   // [i][j]
  const float* __restrict__ Bm = g_U + (size_t)z*LL*DD;   // [j][a]
  float* __restrict__ C = g_FZ + n*LL*DD;
  int m0 = blockIdx.x * 128;
  __shared__ float As[16][129];
  __shared__ float Bs[16][128];
  int tid = threadIdx.x;
  int lr = tid >> 2, lk = (tid & 3)*4;
  int bk = tid >> 5, bn = (tid & 31)*4;
  int rc = (tid >> 4)*4, cc = (tid & 15)*4;
  float acc[8][8];
  #pragma unroll
  for (int i=0;i<8;i++)
    #pragma unroll
    for (int j=0;j<8;j++) acc[i][j] = 0.f;
  for (int k0=0;k0<LL;k0+=16) {
    #pragma unroll
    for (int s=0;s<2;s++) {
      int m = lr + 64*s;
      float4 v = *(const float4*)(A + (size_t)(m0+m)*LL + k0 + lk);
      As[lk+0][m]=v.x; As[lk+1][m]=v.y; As[lk+2][m]=v.z; As[lk+3][m]=v.w;
    }
    #pragma unroll
    for (int s=0;s<2;s++) {
      int k = bk + 8*s;
      *(float4*)&Bs[k][bn] = *(const float4*)(Bm + (k0+k)*DD + bn);
    }
    __syncthreads();
    #pragma unroll
    for (int k=0;k<16;k++) {
      float ar[8], br[8];
      #pragma unroll
      for (int i=0;i<4;i++) { ar[i]=As[k][rc+i]; ar[i+4]=As[k][rc+64+i]; }
      float4 b0 = *(const float4*)&Bs[k][cc];
      float4 b1 = *(const float4*)&Bs[k][cc+64];
      br[0]=b0.x; br[1]=b0.y; br[2]=b0.z; br[3]=b0.w;
      br[4]=b1.x; br[5]=b1.y; br[6]=b1.z; br[7]=b1.w;
      #pragma unroll
      for (int i=0;i<8;i++)
        #pragma unroll
        for (int j=0;j<8;j++)
          acc[i][j] += ar[i]*br[j];
    }
    __syncthreads();
  }
  #pragma unroll
  for (int i=0;i<8;i++) {
    int row = m0 + rc + (i&3) + (i>>2)*64;
    #pragma unroll
    for (int j=0;j<8;j++)
      atomicAdd(C + row*DD + cc + (j&3) + (j>>2)*64, acc[i][j]);
  }
}

// ---------------- msg_j: F_Z += Qhs^T @ P  (TN, K=1024, atomic over h) ----------------
__global__ __launch_bounds__(256) void k_msg_j() {
  int z = blockIdx.z; int n = z >> 3;
  const float* __restrict__ A  = g_S + (size_t)z*LL*LL;   // access [k=i][m=j]
  const float* __restrict__ Bm = g_P + (size_t)z*LL*DD;   // [i][b]
  float* __restrict__ C = g_FZ + n*LL*DD;
  int m0 = blockIdx.x * 128;
  __shared__ float As[16][128];
  __shared__ float Bs[16][128];
  int tid = threadIdx.x;
  int bk = tid >> 5, bn = (tid & 31)*4;
  int rc = (tid >> 4)*4, cc = (tid & 15)*4;
  float acc[8][8];
  #pragma unroll
  for (int i=0;i<8;i++)
    #pragma unroll
    for (int j=0;j<8;j++) acc[i][j] = 0.f;
  for (int k0=0;k0<LL;k0+=16) {
    #pragma unroll
    for (int s=0;s<2;s++) {
      int k = bk + 8*s;
      *(float4*)&As[k][bn] = *(const float4*)(A + (size_t)(k0+k)*LL + m0 + bn);
    }
    #pragma unroll
    for (int s=0;s<2;s++) {
      int k = bk + 8*s;
      *(float4*)&Bs[k][bn] = *(const float4*)(Bm + (k0+k)*DD + bn);
    }
    __syncthreads();
    #pragma unroll
    for (int k=0;k<16;k++) {
      float ar[8], br[8];
      float4 a0 = *(const float4*)&As[k][rc];
      float4 a1 = *(const float4*)&As[k][rc+64];
      ar[0]=a0.x; ar[1]=a0.y; ar[2]=a0.z; ar[3]=a0.w;
      ar[4]=a1.x; ar[5]=a1.y; ar[6]=a1.z; ar[7]=a1.w;
      float4 b0 = *(const float4*)&Bs[k][cc];
      float4 b1 = *(const float4*)&Bs[k][cc+64];
      br[0]=b0.x; br[1]=b0.y; br[2]=b0.z; br[3]=b0.w;
      br[4]=b1.x; br[5]=b1.y; br[6]=b1.z; br[7]=b1.w;
      #pragma unroll
      for (int i=0;i<8;i++)
        #pragma unroll
        for (int j=0;j<8;j++)
          acc[i][j] += ar[i]*br[j];
    }
    __syncthreads();
  }
  #pragma unroll
  for (int i=0;i<8;i++) {
    int row = m0 + rc + (i&3) + (i>>2)*64;
    #pragma unroll
    for (int j=0;j<8;j++)
      atomicAdd(C + row*DD + cc + (j&3) + (j>>2)*64, acc[i][j]);
  }
}

// ---------------- msg_g: F_Z += Qhg_h @ Gp_h (NN, K=64, atomic over h) ----------------
__global__ __launch_bounds__(256) void k_msg_g() {
  int z = blockIdx.z; int n = z >> 3; int h = z & 7;
  const float* __restrict__ A  = g_Hg + (size_t)z*LL*GG;  // [i][g] lda=GG
  const float* __restrict__ Bm = g_Gp + h*GG*DD;          // [g][a] ldb=DD
  float* __restrict__ C = g_FZ + n*LL*DD;
  int m0 = blockIdx.x * 128;
  __shared__ float As[16][129];
  __shared__ float Bs[16][128];
  int tid = threadIdx.x;
  int lr = tid >> 2, lk = (tid & 3)*4;
  int bk = tid >> 5, bn = (tid & 31)*4;
  int rc = (tid >> 4)*4, cc = (tid & 15)*4;
  float acc[8][8];
  #pragma unroll
  for (int i=0;i<8;i++)
    #pragma unroll
    for (int j=0;j<8;j++) acc[i][j] = 0.f;
  for (int k0=0;k0<GG;k0+=16) {
    #pragma unroll
    for (int s=0;s<2;s++) {
      int m = lr + 64*s;
      float4 v = *(const float4*)(A + (m0+m)*GG + k0 + lk);
      As[lk+0][m]=v.x; As[lk+1][m]=v.y; As[lk+2][m]=v.z; As[lk+3][m]=v.w;
    }
    #pragma unroll
    for (int s=0;s<2;s++) {
      int k = bk + 8*s;
      *(float4*)&Bs[k][bn] = *(const float4*)(Bm + (k0+k)*DD + bn);
    }
    __syncthreads();
    #pragma unroll
    for (int k=0;k<16;k++) {
      float ar[8], br[8];
      #pragma unroll
      for (int i=0;i<4;i++) { ar[i]=As[k][rc+i]; ar[i+4]=As[k][rc+64+i]; }
      float4 b0 = *(const float4*)&Bs[k][cc];
      float4 b1 = *(const float4*)&Bs[k][cc+64];
      br[0]=b0.x; br[1]=b0.y; br[2]=b0.z; br[3]=b0.w;
      br[4]=b1.x; br[5]=b1.y; br[6]=b1.z; br[7]=b1.w;
      #pragma unroll
      for (int i=0;i<8;i++)
        #pragma unroll
        for (int j=0;j<8;j++)
          acc[i][j] += ar[i]*br[j];
    }
    __syncthreads();
  }
  #pragma unroll
  for (int i=0;i<8;i++) {
    int row = m0 + rc + (i&3) + (i>>2)*64;
    #pragma unroll
    for (int j=0;j<8;j++)
      atomicAdd(C + row*DD + cc + (j&3) + (j>>2)*64, acc[i][j]);
  }
}

// ---------------- output masking ----------------
__global__ void k_out(const int* __restrict__ mask, float* __restrict__ out) {
  int idx = blockIdx.x*256 + threadIdx.x;
  int ni = idx >> 7;
  out[idx] = mask[ni] ? g_FZ[idx] : 0.f;
}

// ---------------- launch ----------------
extern "C" void kernel_launch(void* const* d_in, const int* in_sizes, int n_in,
                              void* d_out, int out_size) {
  const float* x       = (const float*)d_in[0];
  const int*   mask    = (const int*)  d_in[1];
  const float* ternary = (const float*)d_in[2];
  const float* glob    = (const float*)d_in[3];
  float* out = (float*)d_out;

  k_repack<<<512,256>>>(ternary, glob);
  k_softmax_z<<<BB*LL, DD>>>(x, 0);

  for (int it = 0; it < NITER; it++) {
    k_gemm_zT<<<dim3(8,1,32),256>>>(0);          // P
    k_gemm_zT<<<dim3(8,1,32),256>>>(1);          // U
    k_gemm_hg<<<dim3(8,1,32),256>>>();           // F_Hg
    k_gemm_s <<<dim3(8,8,32),256>>>();           // F_Hs
    k_softmax_h<<<BB*HH*LL,256>>>(mask);         // Q_H (in-place S + Hg)
    k_init_fz<<<(BB*LL*DD)/256,256>>>(x);        // F_Z = x
    k_msg_i<<<dim3(8,1,32),256>>>();             // += Qhs @ U
    k_msg_j<<<dim3(8,1,32),256>>>();             // += Qhs^T @ P
    k_msg_g<<<dim3(8,1,32),256>>>();             // += Qhg @ Gp
    if (it < NITER-1) k_softmax_z<<<BB*LL, DD>>>(x, 1);
  }
  k_out<<<(BB*LL*DD)/256,256>>>(mask, out);
}

// round 5
// speedup vs baseline: 1.9853x; 1.9853x over previous
#include <cuda_runtime.h>
#include <cuda_fp16.h>
#include <cstdint>

#define BB 4
#define LL 1024
#define DD 128
#define HH 8
#define GG 64
#define NEGV -1000000000.0f
#define NITER 4
#define NZ (BB*HH)

// ---------------- scratch (static device arrays; no allocations) ----------------
__device__ float g_FZ[BB*LL*DD];
__device__ float g_S [(size_t)NZ*LL*LL];          // fp32 pair logits (134MB)
__device__ float g_Hg[NZ*LL*GG];                  // fp32 global logits
__device__ __half hQz[BB*LL*DD];                  // softmax(F_Z)
__device__ __half hP [NZ*LL*DD];                  // P[i,b]
__device__ __half hPt[NZ*DD*LL];                  // P^T[b,i]
__device__ __half hUt[NZ*DD*LL];                  // U^T[a,j]
__device__ __half hQ [(size_t)NZ*LL*LL];          // Qhs probabilities
__device__ __half hQt[(size_t)NZ*LL*LL];          // Qhs^T
__device__ __half hHg[NZ*LL*GG];                  // Qhg probabilities
__device__ __half hT [HH*DD*DD];                  // T[h][a][b]
__device__ __half hTt[HH*DD*DD];                  // T[h][b][a]
__device__ __half hG [HH*128*DD];                 // G[h][g][a], g padded to 128
__device__ __half hGt[HH*DD*GG];                  // G^T[h][a][g]

// ---------------- mma.sync GEMM core (D[m,n] += sum_k A[m,k]*B[n,k]) ----------------
// BM=128, BN=128, BK=32, 256 threads (8 warps as 4m x 2n), warp tile 32x64.
#define SROW 40              // padded smem row stride in halves (80B)
#define BUFB 10240           // one buffer = 128*40*2 bytes

__device__ __forceinline__ void load_tile(uint32_t sbase, const __half* G, int ld, int k0, int tid) {
  #pragma unroll
  for (int i = 0; i < 2; i++) {
    int c = tid + i*256;                    // 0..511
    int row = c >> 2, ko = (c & 3) * 8;
    uint32_t dst = sbase + (row*SROW + ko) * 2;
    const __half* src = G + (size_t)row*ld + k0 + ko;
    asm volatile("cp.async.cg.shared.global [%0], [%1], 16;" :: "r"(dst), "l"(src));
  }
}

__device__ __forceinline__ void gemm_acc(
    const __half* A, int lda, const __half* B, int ldb, int K,
    float (&c)[2][8][4], uint32_t sA, uint32_t sB,
    int tid, int wm, int wn, int lane)
{
  int NK = K >> 5;
  load_tile(sA, A, lda, 0, tid);
  load_tile(sB, B, ldb, 0, tid);
  asm volatile("cp.async.commit_group;");
  int sel = lane >> 3, lr = lane & 7;
  for (int kt = 0; kt < NK; kt++) {
    int cur = kt & 1;
    if (kt + 1 < NK) {
      uint32_t nb = (cur ^ 1) * BUFB;
      load_tile(sA + nb, A, lda, (kt+1)*32, tid);
      load_tile(sB + nb, B, ldb, (kt+1)*32, tid);
      asm volatile("cp.async.commit_group;");
      asm volatile("cp.async.wait_group 1;");
    } else {
      asm volatile("cp.async.wait_group 0;");
    }
    __syncthreads();
    uint32_t bufA = sA + cur*BUFB, bufB = sB + cur*BUFB;
    #pragma unroll
    for (int kb = 0; kb < 2; kb++) {
      uint32_t afr[2][4], bfr[4][4];
      #pragma unroll
      for (int mf = 0; mf < 2; mf++) {
        int row = wm*32 + mf*16 + lr + ((sel & 1) ? 8 : 0);
        int col = kb*16 + ((sel & 2) ? 8 : 0);
        uint32_t ad = bufA + (row*SROW + col) * 2;
        asm volatile("ldmatrix.sync.aligned.m8n8.x4.shared.b16 {%0,%1,%2,%3},[%4];"
          : "=r"(afr[mf][0]), "=r"(afr[mf][1]), "=r"(afr[mf][2]), "=r"(afr[mf][3]) : "r"(ad));
      }
      #pragma unroll
      for (int p = 0; p < 4; p++) {
        int row = wn*64 + p*16 + lr + ((sel & 2) ? 8 : 0);
        int col = kb*16 + ((sel & 1) ? 8 : 0);
        uint32_t bd = bufB + (row*SROW + col) * 2;
        asm volatile("ldmatrix.sync.aligned.m8n8.x4.shared.b16 {%0,%1,%2,%3},[%4];"
          : "=r"(bfr[p][0]), "=r"(bfr[p][1]), "=r"(bfr[p][2]), "=r"(bfr[p][3]) : "r"(bd));
      }
      #pragma unroll
      for (int mf = 0; mf < 2; mf++)
        #pragma unroll
        for (int nb = 0; nb < 8; nb++) {
          uint32_t b0 = bfr[nb>>1][(nb&1)*2], b1 = bfr[nb>>1][(nb&1)*2+1];
          asm volatile("mma.sync.aligned.m16n8k16.row.col.f32.f16.f16.f32 "
            "{%0,%1,%2,%3},{%4,%5,%6,%7},{%8,%9},{%0,%1,%2,%3};"
            : "+f"(c[mf][nb][0]), "+f"(c[mf][nb][1]), "+f"(c[mf][nb][2]), "+f"(c[mf][nb][3])
            : "r"(afr[mf][0]), "r"(afr[mf][1]), "r"(afr[mf][2]), "r"(afr[mf][3]),
              "r"(b0), "r"(b1));
        }
    }
    __syncthreads();
  }
}

// MODE: 0=P 1=Ut 2=Pt 3=Hg 4=S
template<int MODE>
__global__ __launch_bounds__(256) void k_g() {
  __shared__ __half sAq[2][128][SROW];
  __shared__ __half sBq[2][128][SROW];
  uint32_t sA = (uint32_t)__cvta_generic_to_shared(&sAq[0][0][0]);
  uint32_t sB = (uint32_t)__cvta_generic_to_shared(&sBq[0][0][0]);
  int tid = threadIdx.x, lane = tid & 31, warp = tid >> 5;
  int wm = warp >> 1, wn = warp & 1;
  int z = blockIdx.z, n = z >> 3, h = z & 7;
  int m0 = 0, n0 = 0;
  const __half *A, *B; int lda, ldb;
  if (MODE == 0) {        // P[i,b] = Qz @ T  (B = Tt[b][a])
    m0 = blockIdx.x * 128;
    A = hQz + (size_t)(n*LL + m0)*DD; lda = DD;
    B = hTt + h*DD*DD; ldb = DD;
  } else if (MODE == 1) { // Ut[a,j]: A=T[a][b], B=Qz[j][b]
    n0 = blockIdx.x * 128;
    A = hT + h*DD*DD; lda = DD;
    B = hQz + (size_t)(n*LL + n0)*DD; ldb = DD;
  } else if (MODE == 2) { // Pt[b,i]: A=Tt[b][a], B=Qz[i][a]
    n0 = blockIdx.x * 128;
    A = hTt + h*DD*DD; lda = DD;
    B = hQz + (size_t)(n*LL + n0)*DD; ldb = DD;
  } else if (MODE == 3) { // Hg[i,g]: A=Qz[i][a], B=G[g][a] (g padded to 128)
    m0 = blockIdx.x * 128;
    A = hQz + (size_t)(n*LL + m0)*DD; lda = DD;
    B = hG + h*128*DD; ldb = DD;
  } else {                // S[i,j]: A=P[i][b], B=Qz[j][b]
    m0 = blockIdx.x * 128; n0 = blockIdx.y * 128;
    A = hP + (size_t)(z*LL + m0)*DD; lda = DD;
    B = hQz + (size_t)(n*LL + n0)*DD; ldb = DD;
  }
  float c[2][8][4];
  #pragma unroll
  for (int i=0;i<2;i++)
    #pragma unroll
    for (int j=0;j<8;j++)
      #pragma unroll
      for (int k=0;k<4;k++) c[i][j][k] = 0.f;

  gemm_acc(A, lda, B, ldb, DD, c, sA, sB, tid, wm, wn, lane);

  #pragma unroll
  for (int mf = 0; mf < 2; mf++)
    #pragma unroll
    for (int rr = 0; rr < 2; rr++) {
      int row = wm*32 + mf*16 + (lane >> 2) + rr*8;
      #pragma unroll
      for (int nb = 0; nb < 8; nb++) {
        int col = wn*64 + nb*8 + (lane & 3)*2;
        float v0 = c[mf][nb][rr*2], v1 = c[mf][nb][rr*2+1];
        if (MODE == 0) {
          *(half2*)(hP + (size_t)(z*LL + m0 + row)*DD + col) = __floats2half2_rn(v0, v1);
        } else if (MODE == 1) {
          *(half2*)(hUt + (size_t)z*DD*LL + (size_t)row*LL + n0 + col) = __floats2half2_rn(v0, v1);
        } else if (MODE == 2) {
          *(half2*)(hPt + (size_t)z*DD*LL + (size_t)row*LL + n0 + col) = __floats2half2_rn(v0, v1);
        } else if (MODE == 3) {
          if (wn == 0) *(float2*)(g_Hg + (size_t)(z*LL + m0 + row)*GG + col) = make_float2(v0, v1);
        } else {
          *(float2*)(g_S + (size_t)(z*LL + m0 + row)*LL + n0 + col) = make_float2(v0, v1);
        }
      }
    }
}

// fused msg_i + msg_j + msg_g, split-K over head groups (2 heads/block), atomic into F_Z
__global__ __launch_bounds__(256) void k_msg() {
  __shared__ __half sAq[2][128][SROW];
  __shared__ __half sBq[2][128][SROW];
  uint32_t sA = (uint32_t)__cvta_generic_to_shared(&sAq[0][0][0]);
  uint32_t sB = (uint32_t)__cvta_generic_to_shared(&sBq[0][0][0]);
  int tid = threadIdx.x, lane = tid & 31, warp = tid >> 5;
  int wm = warp >> 1, wn = warp & 1;
  int bz = blockIdx.z;
  int n = bz >> 2, hg = bz & 3;
  int m0 = blockIdx.x * 128;
  float c[2][8][4];
  #pragma unroll
  for (int i=0;i<2;i++)
    #pragma unroll
    for (int j=0;j<8;j++)
      #pragma unroll
      for (int k=0;k<4;k++) c[i][j][k] = 0.f;

  for (int hh = 0; hh < 2; hh++) {
    int h = hg*2 + hh;
    int z = n*8 + h;
    // msg_i: Q[i,j] x Ut[a,j]
    gemm_acc(hQ + (size_t)z*LL*LL + (size_t)m0*LL, LL,
             hUt + (size_t)z*DD*LL, LL, LL, c, sA, sB, tid, wm, wn, lane);
    // msg_j: Qt[j,i] x Pt[b,i]
    gemm_acc(hQt + (size_t)z*LL*LL + (size_t)m0*LL, LL,
             hPt + (size_t)z*DD*LL, LL, LL, c, sA, sB, tid, wm, wn, lane);
    // msg_g: Qhg[i,g] x Gt[a,g]
    gemm_acc(hHg + (size_t)(z*LL + m0)*GG, GG,
             hGt + h*DD*GG, GG, GG, c, sA, sB, tid, wm, wn, lane);
  }

  float* Cb = g_FZ + (size_t)(n*LL + m0)*DD;
  #pragma unroll
  for (int mf = 0; mf < 2; mf++)
    #pragma unroll
    for (int rr = 0; rr < 2; rr++) {
      int row = wm*32 + mf*16 + (lane >> 2) + rr*8;
      #pragma unroll
      for (int nb = 0; nb < 8; nb++) {
        int col = wn*64 + nb*8 + (lane & 3)*2;
        atomicAdd(Cb + (size_t)row*DD + col,     c[mf][nb][rr*2]);
        atomicAdd(Cb + (size_t)row*DD + col + 1, c[mf][nb][rr*2+1]);
      }
    }
}

// ---------------- repack weights to fp16 (+ transposes, padding) ----------------
__global__ void k_repack(const float* __restrict__ ternary, const float* __restrict__ glob) {
  int idx = blockIdx.x*256 + threadIdx.x;     // 0..131071
  if (idx < DD*DD*HH) {
    int h = idx % HH; int ab = idx / HH; int b = ab % DD; int a = ab / DD;
    __half v = __float2half(ternary[idx]);
    hT [(h*DD + a)*DD + b] = v;
    hTt[(h*DD + b)*DD + a] = v;
  }
  {
    int h = idx / (128*DD); int rem = idx % (128*DD); int g = rem / DD; int a = rem % DD;
    float gv = (g < GG) ? glob[(g*DD + a)*HH + h] : 0.f;
    hG[idx] = __float2half(gv);
    if (g < GG) hGt[(h*DD + a)*GG + g] = __float2half(gv);
  }
}

// ---------------- softmax over D=128 -> hQz ----------------
__global__ void k_softmax_z(const float* __restrict__ x, int use_fz) {
  const float* in = use_fz ? g_FZ : x;
  int row = blockIdx.x; int t = threadIdx.x;  // 128
  float v = in[row*DD + t];
  __shared__ float r1[4], r2[4];
  float m = v;
  #pragma unroll
  for (int o=16;o;o>>=1) m = fmaxf(m, __shfl_xor_sync(0xffffffffu, m, o));
  if ((t&31)==0) r1[t>>5] = m;
  __syncthreads();
  m = fmaxf(fmaxf(r1[0],r1[1]), fmaxf(r1[2],r1[3]));
  float e = __expf(v - m);
  float s = e;
  #pragma unroll
  for (int o=16;o;o>>=1) s += __shfl_xor_sync(0xffffffffu, s, o);
  if ((t&31)==0) r2[t>>5] = s;
  __syncthreads();
  s = r2[0]+r2[1]+r2[2]+r2[3];
  hQz[row*DD + t] = __float2half(e * (1.0f/s));
}

// ---------------- softmax over concat [S row (1024) | Hg row (64)] -> hQ, hHg ----------------
__global__ void k_softmax_h(const int* __restrict__ mask) {
  int r = blockIdx.x;                 // z*L + i
  int t = threadIdx.x;                // 256
  const float* Srow = g_S  + (size_t)r*LL;
  const float* Hrow = g_Hg + (size_t)r*GG;
  int n = r >> 13;
  int i = r & (LL-1);
  const int* mrow = mask + n*LL;
  int mi = mrow[i];
  float v[4];
  float lm = -3.4e38f;
  #pragma unroll
  for (int s=0;s<4;s++) {
    int j = t + s*256;
    float xv = Srow[j];
    if (!(mi && mrow[j])) xv = NEGV;
    v[s] = xv; lm = fmaxf(lm, xv);
  }
  float hgv = 0.f;
  if (t < GG) { hgv = Hrow[t]; lm = fmaxf(lm, hgv); }
  __shared__ float sm[8], ss[8];
  float w = lm;
  #pragma unroll
  for (int o=16;o;o>>=1) w = fmaxf(w, __shfl_xor_sync(0xffffffffu, w, o));
  if ((t&31)==0) sm[t>>5] = w;
  __syncthreads();
  float m = sm[0];
  #pragma unroll
  for (int q=1;q<8;q++) m = fmaxf(m, sm[q]);
  float sum = 0.f;
  #pragma unroll
  for (int s=0;s<4;s++) { v[s] = __expf(v[s]-m); sum += v[s]; }
  if (t < GG) { hgv = __expf(hgv-m); sum += hgv; }
  #pragma unroll
  for (int o=16;o;o>>=1) sum += __shfl_xor_sync(0xffffffffu, sum, o);
  if ((t&31)==0) ss[t>>5] = sum;
  __syncthreads();
  float tot = 0.f;
  #pragma unroll
  for (int q=0;q<8;q++) tot += ss[q];
  float inv = 1.0f/tot;
  __half* Qrow = hQ + (size_t)r*LL;
  #pragma unroll
  for (int s=0;s<4;s++) Qrow[t+s*256] = __float2half(v[s]*inv);
  if (t < GG) hHg[(size_t)r*GG + t] = __float2half(hgv*inv);
}

// ---------------- fp16 transpose: Qt[j,i] = Q[i,j], 64x64 tiles ----------------
__global__ void k_transQ() {
  __shared__ __half tl[64][72];
  size_t zo = (size_t)blockIdx.z*LL*LL;
  int r0 = blockIdx.y*64, c0 = blockIdx.x*64;
  int tid = threadIdx.x;                // 256
  #pragma unroll
  for (int it=0; it<2; it++) {
    int idx = tid + it*256;             // 0..511
    int row = idx>>3, q = idx&7;
    uint4 v = *(const uint4*)(hQ + zo + (size_t)(r0+row)*LL + c0 + q*8);
    *(uint4*)&tl[row][q*8] = v;
  }
  __syncthreads();
  #pragma unroll
  for (int it=0; it<2; it++) {
    int idx = tid + it*256;
    int orow = idx>>3, q = idx&7;
    alignas(16) __half vv[8];
    #pragma unroll
    for (int k=0;k<8;k++) vv[k] = tl[q*8+k][orow];
    *(uint4*)(hQt + zo + (size_t)(c0+orow)*LL + r0 + q*8) = *(uint4*)vv;
  }
}

// ---------------- F_Z = x ----------------
__global__ void k_init_fz(const float* __restrict__ x) {
  int i = blockIdx.x*256 + threadIdx.x;
  g_FZ[i] = x[i];
}

// ---------------- output masking ----------------
__global__ void k_out(const int* __restrict__ mask, float* __restrict__ out) {
  int idx = blockIdx.x*256 + threadIdx.x;
  int ni = idx >> 7;
  out[idx] = mask[ni] ? g_FZ[idx] : 0.f;
}

// ---------------- launch ----------------
extern "C" void kernel_launch(void* const* d_in, const int* in_sizes, int n_in,
                              void* d_out, int out_size) {
  const float* x       = (const float*)d_in[0];
  const int*   mask    = (const int*)  d_in[1];
  const float* ternary = (const float*)d_in[2];
  const float* glob    = (const float*)d_in[3];
  float* out = (float*)d_out;

  k_repack<<<512,256>>>(ternary, glob);
  k_softmax_z<<<BB*LL, 128>>>(x, 0);

  for (int it = 0; it < NITER; it++) {
    k_g<0><<<dim3(8,1,NZ),256>>>();          // P
    k_g<1><<<dim3(8,1,NZ),256>>>();          // Ut
    k_g<2><<<dim3(8,1,NZ),256>>>();          // Pt
    k_g<3><<<dim3(8,1,NZ),256>>>();          // Hg logits
    k_g<4><<<dim3(8,8,NZ),256>>>();          // S logits
    k_softmax_h<<<NZ*LL, 256>>>(mask);       // -> hQ, hHg
    k_transQ<<<dim3(16,16,NZ),256>>>();      // hQt
    k_init_fz<<<(BB*LL*DD)/256,256>>>(x);    // F_Z = x
    k_msg<<<dim3(8,1,16),256>>>();           // F_Z += msg_i + msg_j + msg_g
    if (it < NITER-1) k_softmax_z<<<BB*LL, 128>>>(x, 1);
  }
  k_out<<<(BB*LL*DD)/256,256>>>(mask, out);
}

// round 8
// speedup vs baseline: 4.1663x; 2.0986x over previous
#include <cuda_runtime.h>
#include <cuda_fp16.h>
#include <cstdint>

#define BB 4
#define LL 1024
#define DD 128
#define HH 8
#define GG 64
#define NEGV -1000000000.0f
#define NITER 4
#define NZ (BB*HH)

// ---------------- scratch (static device arrays; no allocations) ----------------
__device__ float g_FZ[BB*LL*DD];
__device__ float g_S [(size_t)NZ*LL*LL];          // fp32 pair logits (134MB)
__device__ float g_Hg[NZ*LL*GG];                  // fp32 global logits
__device__ __half hQz[BB*LL*DD];                  // softmax(F_Z)
__device__ __half hP [NZ*LL*DD];                  // P[i,b]
__device__ __half hPt[NZ*DD*LL];                  // P^T[b,i]
__device__ __half hUt[NZ*DD*LL];                  // U^T[a,j]
__device__ __half hQ [(size_t)NZ*LL*LL];          // Qhs probabilities
__device__ __half hHg[NZ*LL*GG];                  // Qhg probabilities
__device__ __half hT [HH*DD*DD];                  // T[h][a][b]
__device__ __half hTt[HH*DD*DD];                  // T[h][b][a]
__device__ __half hG [HH*128*DD];                 // G[h][g][a], g padded to 128
__device__ __half hGt[HH*DD*GG];                  // G^T[h][a][g]

// ---------------- mma.sync GEMM core ----------------
// BM=128, BN=128, BK=64, 128 threads (4 warps as 2m x 2n), warp tile 64x64, 3-stage cp.async.
#define SKA 72                   // A-normal / B smem row stride (halves)
#define SKT 136                  // A-trans smem row stride (halves)
#define TILEB 18432              // max tile bytes (128*72*2)
#define STAGEB (2*TILEB)         // A + B per stage
#define NSTG 3
#define SMEMB (NSTG*STAGEB)      // 110592

template<bool TA>
__device__ __forceinline__ void load_A(uint32_t dst, const __half* A, int lda, int kt, int tid) {
  if (!TA) {
    #pragma unroll
    for (int i = 0; i < 8; i++) {
      int idx = tid + i*128;
      int row = idx >> 3, co = (idx & 7) * 8;
      uint32_t d = dst + (row*SKA + co)*2;
      const __half* s = A + (size_t)row*lda + kt*64 + co;
      asm volatile("cp.async.cg.shared.global [%0], [%1], 16;" :: "r"(d), "l"(s));
    }
  } else {
    #pragma unroll
    for (int i = 0; i < 8; i++) {
      int idx = tid + i*128;
      int row = idx >> 4, co = (idx & 15) * 8;
      uint32_t d = dst + (row*SKT + co)*2;
      const __half* s = A + (size_t)(kt*64 + row)*lda + co;
      asm volatile("cp.async.cg.shared.global [%0], [%1], 16;" :: "r"(d), "l"(s));
    }
  }
}
__device__ __forceinline__ void load_B(uint32_t dst, const __half* B, int ldb, int kt, int tid) {
  #pragma unroll
  for (int i = 0; i < 8; i++) {
    int idx = tid + i*128;
    int row = idx >> 3, co = (idx & 7) * 8;
    uint32_t d = dst + (row*SKA + co)*2;
    const __half* s = B + (size_t)row*ldb + kt*64 + co;
    asm volatile("cp.async.cg.shared.global [%0], [%1], 16;" :: "r"(d), "l"(s));
  }
}

template<bool TA>
__device__ __forceinline__ void gemm_acc(
    const __half* A, int lda, const __half* B, int ldb, int K,
    float (&c)[4][8][4], uint32_t sbase, int tid, int wm, int wn, int lane)
{
  int NK = K >> 6;
  int lr = lane & 7, sel = lane >> 3;
  #pragma unroll
  for (int s = 0; s < NSTG-1; s++) {
    if (s < NK) {
      load_A<TA>(sbase + s*STAGEB, A, lda, s, tid);
      load_B(sbase + s*STAGEB + TILEB, B, ldb, s, tid);
    }
    asm volatile("cp.async.commit_group;");
  }
  for (int kt = 0; kt < NK; kt++) {
    int ps = kt + NSTG - 1;
    if (ps < NK) {
      uint32_t sb = sbase + (ps % NSTG)*STAGEB;
      load_A<TA>(sb, A, lda, ps, tid);
      load_B(sb + TILEB, B, ldb, ps, tid);
    }
    asm volatile("cp.async.commit_group;");
    asm volatile("cp.async.wait_group %0;" :: "n"(NSTG-1));
    __syncthreads();
    uint32_t bufA = sbase + (kt % NSTG)*STAGEB;
    uint32_t bufB = bufA + TILEB;
    #pragma unroll
    for (int kb = 0; kb < 4; kb++) {
      uint32_t afr[4][4], bfr[4][4];
      #pragma unroll
      for (int mf = 0; mf < 4; mf++) {
        if (!TA) {
          int row = wm*64 + mf*16 + lr + ((sel & 1) ? 8 : 0);
          int col = kb*16 + ((sel & 2) ? 8 : 0);
          uint32_t ad = bufA + (row*SKA + col)*2;
          asm volatile("ldmatrix.sync.aligned.m8n8.x4.shared.b16 {%0,%1,%2,%3},[%4];"
            : "=r"(afr[mf][0]), "=r"(afr[mf][1]), "=r"(afr[mf][2]), "=r"(afr[mf][3]) : "r"(ad));
        } else {
          int row = kb*16 + lr + ((sel & 2) ? 8 : 0);
          int col = wm*64 + mf*16 + ((sel & 1) ? 8 : 0);
          uint32_t ad = bufA + (row*SKT + col)*2;
          asm volatile("ldmatrix.sync.aligned.m8n8.x4.trans.shared.b16 {%0,%1,%2,%3},[%4];"
            : "=r"(afr[mf][0]), "=r"(afr[mf][1]), "=r"(afr[mf][2]), "=r"(afr[mf][3]) : "r"(ad));
        }
      }
      #pragma unroll
      for (int p = 0; p < 4; p++) {
        int row = wn*64 + p*16 + lr + ((sel & 2) ? 8 : 0);
        int col = kb*16 + ((sel & 1) ? 8 : 0);
        uint32_t bd = bufB + (row*SKA + col)*2;
        asm volatile("ldmatrix.sync.aligned.m8n8.x4.shared.b16 {%0,%1,%2,%3},[%4];"
          : "=r"(bfr[p][0]), "=r"(bfr[p][1]), "=r"(bfr[p][2]), "=r"(bfr[p][3]) : "r"(bd));
      }
      #pragma unroll
      for (int mf = 0; mf < 4; mf++)
        #pragma unroll
        for (int nb = 0; nb < 8; nb++) {
          asm volatile("mma.sync.aligned.m16n8k16.row.col.f32.f16.f16.f32 "
            "{%0,%1,%2,%3},{%4,%5,%6,%7},{%8,%9},{%0,%1,%2,%3};"
            : "+f"(c[mf][nb][0]), "+f"(c[mf][nb][1]), "+f"(c[mf][nb][2]), "+f"(c[mf][nb][3])
            : "r"(afr[mf][0]), "r"(afr[mf][1]), "r"(afr[mf][2]), "r"(afr[mf][3]),
              "r"(bfr[nb>>1][(nb&1)*2]), "r"(bfr[nb>>1][(nb&1)*2+1]));
        }
    }
    __syncthreads();
  }
}

// ---------------- merged projection kernel: mode = blockIdx.y ----------------
// 0: P[i,b]=Qz@T   1: Ut[a,j]=T@Qz^T   2: Pt[b,i]=Tt@Qz^T   3: Hg[i,g]=Qz@G^T
__global__ __launch_bounds__(128, 2) void k_proj() {
  extern __shared__ char smem[];
  uint32_t sbase = (uint32_t)__cvta_generic_to_shared(smem);
  int tid = threadIdx.x, lane = tid & 31, warp = tid >> 5;
  int wm = warp >> 1, wn = warp & 1;
  int mode = blockIdx.y;
  int z = blockIdx.z, n = z >> 3, h = z & 7;
  int m0 = 0, n0 = 0;
  const __half *A, *B;
  if (mode == 0) {
    m0 = blockIdx.x * 128;
    A = hQz + (size_t)(n*LL + m0)*DD;
    B = hTt + h*DD*DD;
  } else if (mode == 1) {
    n0 = blockIdx.x * 128;
    A = hT + h*DD*DD;
    B = hQz + (size_t)(n*LL + n0)*DD;
  } else if (mode == 2) {
    n0 = blockIdx.x * 128;
    A = hTt + h*DD*DD;
    B = hQz + (size_t)(n*LL + n0)*DD;
  } else {
    m0 = blockIdx.x * 128;
    A = hQz + (size_t)(n*LL + m0)*DD;
    B = hG + h*128*DD;
  }
  float c[4][8][4];
  #pragma unroll
  for (int i=0;i<4;i++)
    #pragma unroll
    for (int j=0;j<8;j++)
      #pragma unroll
      for (int k=0;k<4;k++) c[i][j][k] = 0.f;

  gemm_acc<false>(A, DD, B, DD, DD, c, sbase, tid, wm, wn, lane);

  #pragma unroll
  for (int mf = 0; mf < 4; mf++)
    #pragma unroll
    for (int rr = 0; rr < 2; rr++) {
      int row = wm*64 + mf*16 + (lane >> 2) + rr*8;
      #pragma unroll
      for (int nb = 0; nb < 8; nb++) {
        int col = wn*64 + nb*8 + (lane & 3)*2;
        float v0 = c[mf][nb][rr*2], v1 = c[mf][nb][rr*2+1];
        if (mode == 0) {
          *(half2*)(hP + (size_t)(z*LL + m0 + row)*DD + col) = __floats2half2_rn(v0, v1);
        } else if (mode == 1) {
          *(half2*)(hUt + (size_t)z*DD*LL + (size_t)row*LL + n0 + col) = __floats2half2_rn(v0, v1);
        } else if (mode == 2) {
          *(half2*)(hPt + (size_t)z*DD*LL + (size_t)row*LL + n0 + col) = __floats2half2_rn(v0, v1);
        } else {
          if (wn == 0)
            *(float2*)(g_Hg + (size_t)(z*LL + m0 + row)*GG + col) = make_float2(v0, v1);
        }
      }
    }
}

// ---------------- S[i,j] = P @ Qz^T ----------------
__global__ __launch_bounds__(128, 2) void k_S() {
  extern __shared__ char smem[];
  uint32_t sbase = (uint32_t)__cvta_generic_to_shared(smem);
  int tid = threadIdx.x, lane = tid & 31, warp = tid >> 5;
  int wm = warp >> 1, wn = warp & 1;
  int z = blockIdx.z, n = z >> 3;
  int m0 = blockIdx.x * 128, n0 = blockIdx.y * 128;
  const __half* A = hP + (size_t)(z*LL + m0)*DD;
  const __half* B = hQz + (size_t)(n*LL + n0)*DD;
  float c[4][8][4];
  #pragma unroll
  for (int i=0;i<4;i++)
    #pragma unroll
    for (int j=0;j<8;j++)
      #pragma unroll
      for (int k=0;k<4;k++) c[i][j][k] = 0.f;

  gemm_acc<false>(A, DD, B, DD, DD, c, sbase, tid, wm, wn, lane);

  #pragma unroll
  for (int mf = 0; mf < 4; mf++)
    #pragma unroll
    for (int rr = 0; rr < 2; rr++) {
      int row = wm*64 + mf*16 + (lane >> 2) + rr*8;
      #pragma unroll
      for (int nb = 0; nb < 8; nb++) {
        int col = wn*64 + nb*8 + (lane & 3)*2;
        *(float2*)(g_S + (size_t)(z*LL + m0 + row)*LL + n0 + col) =
            make_float2(c[mf][nb][rr*2], c[mf][nb][rr*2+1]);
      }
    }
}

// ---------------- fused msg_i + msg_j + msg_g per head, atomic into F_Z ----------------
__global__ __launch_bounds__(128, 2) void k_msg() {
  extern __shared__ char smem[];
  uint32_t sbase = (uint32_t)__cvta_generic_to_shared(smem);
  int tid = threadIdx.x, lane = tid & 31, warp = tid >> 5;
  int wm = warp >> 1, wn = warp & 1;
  int z = blockIdx.z, n = z >> 3, h = z & 7;
  int m0 = blockIdx.x * 128;
  float c[4][8][4];
  #pragma unroll
  for (int i=0;i<4;i++)
    #pragma unroll
    for (int j=0;j<8;j++)
      #pragma unroll
      for (int k=0;k<4;k++) c[i][j][k] = 0.f;

  // msg_i[i,a]: A = Q[i,j] rows m0.., B = Ut[a,j]
  gemm_acc<false>(hQ + (size_t)z*LL*LL + (size_t)m0*LL, LL,
                  hUt + (size_t)z*DD*LL, LL, LL, c, sbase, tid, wm, wn, lane);
  // msg_j[j,b]: A = Q^T via ldmatrix.trans (tile = Q rows k, cols m0..), B = Pt[b,i]
  gemm_acc<true>(hQ + (size_t)z*LL*LL + m0, LL,
                 hPt + (size_t)z*DD*LL, LL, LL, c, sbase, tid, wm, wn, lane);
  // msg_g[i,a]: A = Qhg[i,g], B = Gt[a,g]
  gemm_acc<false>(hHg + (size_t)(z*LL + m0)*GG, GG,
                  hGt + h*DD*GG, GG, GG, c, sbase, tid, wm, wn, lane);

  float* Cb = g_FZ + (size_t)(n*LL + m0)*DD;
  #pragma unroll
  for (int mf = 0; mf < 4; mf++)
    #pragma unroll
    for (int rr = 0; rr < 2; rr++) {
      int row = wm*64 + mf*16 + (lane >> 2) + rr*8;
      #pragma unroll
      for (int nb = 0; nb < 8; nb++) {
        int col = wn*64 + nb*8 + (lane & 3)*2;
        atomicAdd(Cb + (size_t)row*DD + col,     c[mf][nb][rr*2]);
        atomicAdd(Cb + (size_t)row*DD + col + 1, c[mf][nb][rr*2+1]);
      }
    }
}

// ---------------- repack weights to fp16 (+ transposes, padding) ----------------
__global__ void k_repack(const float* __restrict__ ternary, const float* __restrict__ glob) {
  int idx = blockIdx.x*256 + threadIdx.x;     // 0..131071
  if (idx < DD*DD*HH) {
    int h = idx % HH; int ab = idx / HH; int b = ab % DD; int a = ab / DD;
    __half v = __float2half(ternary[idx]);
    hT [(h*DD + a)*DD + b] = v;
    hTt[(h*DD + b)*DD + a] = v;
  }
  {
    int h = idx / (128*DD); int rem = idx % (128*DD); int g = rem / DD; int a = rem % DD;
    float gv = (g < GG) ? glob[(g*DD + a)*HH + h] : 0.f;
    hG[idx] = __float2half(gv);
    if (g < GG) hGt[(h*DD + a)*GG + g] = __float2half(gv);
  }
}

// ---------------- softmax over D=128 -> hQz ----------------
__global__ void k_softmax_z(const float* __restrict__ x, int use_fz) {
  const float* in = use_fz ? g_FZ : x;
  int row = blockIdx.x; int t = threadIdx.x;  // 128
  float v = in[row*DD + t];
  __shared__ float r1[4], r2[4];
  float m = v;
  #pragma unroll
  for (int o=16;o;o>>=1) m = fmaxf(m, __shfl_xor_sync(0xffffffffu, m, o));
  if ((t&31)==0) r1[t>>5] = m;
  __syncthreads();
  m = fmaxf(fmaxf(r1[0],r1[1]), fmaxf(r1[2],r1[3]));
  float e = __expf(v - m);
  float s = e;
  #pragma unroll
  for (int o=16;o;o>>=1) s += __shfl_xor_sync(0xffffffffu, s, o);
  if ((t&31)==0) r2[t>>5] = s;
  __syncthreads();
  s = r2[0]+r2[1]+r2[2]+r2[3];
  hQz[row*DD + t] = __float2half(e * (1.0f/s));
}

// ---------------- softmax over concat [S row (1024) | Hg row (64)] -> hQ, hHg ----------------
__global__ void k_softmax_h(const int* __restrict__ mask) {
  int r = blockIdx.x;                 // z*L + i
  int t = threadIdx.x;                // 256
  const float* Srow = g_S  + (size_t)r*LL;
  const float* Hrow = g_Hg + (size_t)r*GG;
  int n = r >> 13;
  int i = r & (LL-1);
  const int* mrow = mask + n*LL;
  int mi = mrow[i];
  float v[4];
  float lm = -3.4e38f;
  #pragma unroll
  for (int s=0;s<4;s++) {
    int j = t + s*256;
    float xv = Srow[j];
    if (!(mi && mrow[j])) xv = NEGV;
    v[s] = xv; lm = fmaxf(lm, xv);
  }
  float hgv = 0.f;
  if (t < GG) { hgv = Hrow[t]; lm = fmaxf(lm, hgv); }
  __shared__ float sm[8], ss[8];
  float w = lm;
  #pragma unroll
  for (int o=16;o;o>>=1) w = fmaxf(w, __shfl_xor_sync(0xffffffffu, w, o));
  if ((t&31)==0) sm[t>>5] = w;
  __syncthreads();
  float m = sm[0];
  #pragma unroll
  for (int q=1;q<8;q++) m = fmaxf(m, sm[q]);
  float sum = 0.f;
  #pragma unroll
  for (int s=0;s<4;s++) { v[s] = __expf(v[s]-m); sum += v[s]; }
  if (t < GG) { hgv = __expf(hgv-m); sum += hgv; }
  #pragma unroll
  for (int o=16;o;o>>=1) sum += __shfl_xor_sync(0xffffffffu, sum, o);
  if ((t&31)==0) ss[t>>5] = sum;
  __syncthreads();
  float tot = 0.f;
  #pragma unroll
  for (int q=0;q<8;q++) tot += ss[q];
  float inv = 1.0f/tot;
  __half* Qrow = hQ + (size_t)r*LL;
  #pragma unroll
  for (int s=0;s<4;s++) Qrow[t+s*256] = __float2half(v[s]*inv);
  if (t < GG) hHg[(size_t)r*GG + t] = __float2half(hgv*inv);
}

// ---------------- F_Z = x ----------------
__global__ void k_init_fz(const float* __restrict__ x) {
  int i = blockIdx.x*256 + threadIdx.x;
  g_FZ[i] = x[i];
}

// ---------------- output masking ----------------
__global__ void k_out(const int* __restrict__ mask, float* __restrict__ out) {
  int idx = blockIdx.x*256 + threadIdx.x;
  int ni = idx >> 7;
  out[idx] = mask[ni] ? g_FZ[idx] : 0.f;
}

// ---------------- launch ----------------
extern "C" void kernel_launch(void* const* d_in, const int* in_sizes, int n_in,
                              void* d_out, int out_size) {
  const float* x       = (const float*)d_in[0];
  const int*   mask    = (const int*)  d_in[1];
  const float* ternary = (const float*)d_in[2];
  const float* glob    = (const float*)d_in[3];
  float* out = (float*)d_out;

  cudaFuncSetAttribute(k_proj, cudaFuncAttributeMaxDynamicSharedMemorySize, SMEMB);
  cudaFuncSetAttribute(k_S,    cudaFuncAttributeMaxDynamicSharedMemorySize, SMEMB);
  cudaFuncSetAttribute(k_msg,  cudaFuncAttributeMaxDynamicSharedMemorySize, SMEMB);

  k_repack<<<512,256>>>(ternary, glob);
  k_softmax_z<<<BB*LL, 128>>>(x, 0);

  for (int it = 0; it < NITER; it++) {
    k_proj<<<dim3(8,4,NZ),128,SMEMB>>>();     // P, Ut, Pt, Hg logits
    k_S   <<<dim3(8,8,NZ),128,SMEMB>>>();     // S logits
    k_softmax_h<<<NZ*LL, 256>>>(mask);        // -> hQ, hHg
    k_init_fz<<<(BB*LL*DD)/256,256>>>(x);     // F_Z = x
    k_msg <<<dim3(8,1,NZ),128,SMEMB>>>();     // F_Z += msg_i + msg_j + msg_g
    if (it < NITER-1) k_softmax_z<<<BB*LL, 128>>>(x, 1);
  }
  k_out<<<(BB*LL*DD)/256,256>>>(mask, out);
}